// round 2
// baseline (speedup 1.0000x reference)
#include <cuda_runtime.h>

// Problem constants (fixed by setup_inputs): B=8, H=W=512, D=32, K=64
#define BATCH   8
#define NPIX    (512 * 512)
#define DIM     32
#define KINST   64
#define MARGIN  0.25f

#define BPB     111                // blocks per batch; 111*8 = 888 = 148 SMs * 6
#define THREADS 128
#define WARPS   (THREADS / 32)     // 4
#define CHUNK   ((NPIX + BPB - 1) / BPB)

// Scratch (allocs are banned; __device__ globals are the sanctioned path)
__device__ float g_sums[BATCH * KINST * DIM];
__device__ float g_counts[BATCH * KINST];

// ---------------------------------------------------------------------------
// Kernel 0: zero scratch + output
// ---------------------------------------------------------------------------
__global__ void zero_kernel(float* __restrict__ out) {
    int i = blockIdx.x * blockDim.x + threadIdx.x;
    if (i < BATCH * KINST * DIM) g_sums[i] = 0.0f;
    if (i < BATCH * KINST)       g_counts[i] = 0.0f;
    if (i == 0)                  out[0] = 0.0f;
}

// ---------------------------------------------------------------------------
// Kernel 1: segment accumulation.
// Warp-private smem bins: lane d owns dimension d -> race-free and
// bank-conflict-free (smem word index = ... + lane => bank == lane).
// grid = (BPB, BATCH), block = 128 threads (4 warps).
// Static smem: 4*8KB bins + 1KB counts = 33KB -> 6 blocks/SM, 24 warps/SM.
// ---------------------------------------------------------------------------
__global__ __launch_bounds__(THREADS, 6)
void accum_kernel(const float* __restrict__ emb, const int* __restrict__ lab) {
    __shared__ float bins[WARPS][KINST * DIM];   // 4 * 8KB = 32KB
    __shared__ float cnts[WARPS][KINST];         // 1KB

    const int w    = threadIdx.x >> 5;
    const int lane = threadIdx.x & 31;
    const int b    = blockIdx.y;

    // zero shared
    for (int i = threadIdx.x; i < WARPS * KINST * DIM; i += THREADS)
        (&bins[0][0])[i] = 0.0f;
    for (int i = threadIdx.x; i < WARPS * KINST; i += THREADS)
        (&cnts[0][0])[i] = 0.0f;
    __syncthreads();

    const int p0 = blockIdx.x * CHUNK;
    const int p1 = (p0 + CHUNK < NPIX) ? (p0 + CHUNK) : NPIX;

    const float* __restrict__ e = emb + (size_t)b * NPIX * DIM;
    const int*   __restrict__ l = lab + (size_t)b * NPIX;

    float* mybins = &bins[w][lane];      // index by k*DIM; bank stays == lane
    float* mycnts = &cnts[w][0];

    constexpr int U = 8;
    int p = p0 + w;
    // unrolled main loop: 8 pixels in flight per warp for MLP
    for (; p + (U - 1) * WARPS < p1; p += U * WARPS) {
        float v[U];
        int   kk[U];
#pragma unroll
        for (int u = 0; u < U; u++) {
            const int pp = p + u * WARPS;
            v[u]  = __ldcs(&e[(size_t)pp * DIM + lane]);
            kk[u] = __ldcs(&l[pp]);
        }
#pragma unroll
        for (int u = 0; u < U; u++) {
            mybins[kk[u] * DIM] += v[u];
            if (lane == 0) mycnts[kk[u]] += 1.0f;
        }
    }
    // tail
    for (; p < p1; p += WARPS) {
        float v = __ldcs(&e[(size_t)p * DIM + lane]);
        int  kk = __ldcs(&l[p]);
        mybins[kk * DIM] += v;
        if (lane == 0) mycnts[kk] += 1.0f;
    }
    __syncthreads();

    // block reduce across the 4 warp-private copies, then global atomics
    for (int i = threadIdx.x; i < KINST * DIM; i += THREADS) {
        float s = 0.0f;
#pragma unroll
        for (int ww = 0; ww < WARPS; ww++) s += bins[ww][i];
        atomicAdd(&g_sums[b * KINST * DIM + i], s);
    }
    for (int i = threadIdx.x; i < KINST; i += THREADS) {
        float s = 0.0f;
#pragma unroll
        for (int ww = 0; ww < WARPS; ww++) s += cnts[ww][i];
        atomicAdd(&g_counts[b * KINST + i], s);
    }
}

// ---------------------------------------------------------------------------
// Kernel 2: finalize. One block per batch element.
// Centroids cached in smem with stride-33 padding (bank-conflict-free pair loop).
// ---------------------------------------------------------------------------
#define CSTRIDE 33

__global__ __launch_bounds__(256)
void finalize_kernel(float* __restrict__ out) {
    __shared__ float c[KINST * CSTRIDE];
    __shared__ float cnt[KINST];
    __shared__ float acc_s;

    const int b   = blockIdx.x;
    const int tid = threadIdx.x;

    if (tid == 0) acc_s = 0.0f;
    for (int i = tid; i < KINST; i += blockDim.x)
        cnt[i] = g_counts[b * KINST + i];
    for (int i = tid; i < KINST * DIM; i += blockDim.x) {
        const int k = i / DIM, d = i - k * DIM;
        const float ct = g_counts[b * KINST + k];
        c[k * CSTRIDE + d] = g_sums[b * KINST * DIM + i] / fmaxf(ct, 1.0f);
    }
    __syncthreads();

    float acc = 0.0f;
    for (int t = tid; t < KINST * KINST; t += blockDim.x) {
        const int i = t / KINST, j = t - i * KINST;
        if (j > i && cnt[i] > 0.5f && cnt[j] > 0.5f) {
            float dsum = 0.0f;
#pragma unroll
            for (int d = 0; d < DIM; d++)
                dsum += fabsf(c[i * CSTRIDE + d] - c[j * CSTRIDE + d]);
            const float h = fmaxf(0.0f, MARGIN - dsum);
            acc += h * h;
        }
    }
    // warp reduce
#pragma unroll
    for (int off = 16; off > 0; off >>= 1)
        acc += __shfl_xor_sync(0xFFFFFFFFu, acc, off);
    if ((tid & 31) == 0) atomicAdd(&acc_s, acc);
    __syncthreads();

    if (tid == 0) {
        float n = 0.0f;
#pragma unroll
        for (int k = 0; k < KINST; k++) n += (cnt[k] > 0.5f) ? 1.0f : 0.0f;
        const float ncomp = n * (n - 1.0f) * 0.5f;
        atomicAdd(out, (acc_s / ncomp) * (1.0f / (float)BATCH));
    }
}

// ---------------------------------------------------------------------------
extern "C" void kernel_launch(void* const* d_in, const int* in_sizes, int n_in,
                              void* d_out, int out_size) {
    const float* emb = (const float*)d_in[0];
    const int*   lab = (const int*)d_in[1];
    float*       out = (float*)d_out;
    (void)in_sizes; (void)n_in; (void)out_size;

    zero_kernel<<<(BATCH * KINST * DIM + 255) / 256, 256>>>(out);
    dim3 grid(BPB, BATCH);
    accum_kernel<<<grid, THREADS>>>(emb, lab);
    finalize_kernel<<<BATCH, 256>>>(out);
}